// round 2
// baseline (speedup 1.0000x reference)
#include <cuda_runtime.h>
#include <cstdint>
#include <cstddef>

// Problem constants
#define BB   128      // batch
#define TT   2048     // timesteps
#define UU   256      // units
#define CLS  8        // cluster size (u-split)
#define BPC  8        // batches per cluster
#define UCTA 32       // u per CTA
#define COLS 128      // z columns per CTA (4 gates * UCTA)
#define NTHR 256

// Shared memory layout (bytes)
#define OFF_W   0                      // Wh slice, pair-packed: [128 k2][128 c][2] f32
#define SZ_W    (128*128*2*4)          // 131072
#define OFF_H   (OFF_W + SZ_W)         // h double buffer [2][8][256] f32 = 16384
#define OFF_Z   (OFF_H + 16384)        // z staging [8][128] f32 = 4096
#define OFF_WX  (OFF_Z + 4096)         // Wx slice [3][128] f32 = 1536
#define OFF_BI  (OFF_WX + 1536)        // bias slice [128] f32 = 512
#define OFF_XS  (OFF_BI + 512)         // x values [8][4] f32 = 128
#define SMEM_BYTES (OFF_XS + 128)      // 153728

__device__ __forceinline__ void ffma2(unsigned long long &acc,
                                      unsigned long long a,
                                      unsigned long long w) {
    // packed f32x2 FMA: lo,hi lanes independent MACs
    asm("fma.rn.f32x2 %0, %1, %2, %0;" : "+l"(acc) : "l"(a), "l"(w));
}

__device__ __forceinline__ uint32_t smem_u32(const void* p) {
    uint32_t a;
    asm("{ .reg .u64 t; cvta.to.shared.u64 t, %1; cvt.u32.u64 %0, t; }"
        : "=r"(a) : "l"(p));
    return a;
}

__device__ __forceinline__ void st_cluster_f32(uint32_t saddr, uint32_t rank, float v) {
    uint32_t r;
    asm volatile("mapa.shared::cluster.u32 %0, %1, %2;" : "=r"(r) : "r"(saddr), "r"(rank));
    asm volatile("st.shared::cluster.b32 [%0], %1;" :: "r"(r), "r"(__float_as_uint(v)) : "memory");
}

__device__ __forceinline__ float sigm(float v) {
    return 1.f / (1.f + __expf(-v));
}

__device__ __forceinline__ float tanh_f(float v) {
    float vv = fminf(fmaxf(v, -15.f), 15.f);
    float e = __expf(-2.f * vv);
    return (1.f - e) / (1.f + e);
}

__global__ void __launch_bounds__(NTHR, 1) __cluster_dims__(CLS, 1, 1)
lstm_cluster_kernel(const float* __restrict__ x,     // [B,T,3]
                    const float* __restrict__ Wx,    // [3,1024]
                    const float* __restrict__ Wh,    // [256,1024]
                    const float* __restrict__ bias,  // [1024]
                    float* __restrict__ out, int out_size)
{
    extern __shared__ char sm[];
    float* Wp   = (float*)(sm + OFF_W);
    float* hbuf = (float*)(sm + OFF_H);   // [2][BPC][UU]
    float* zs   = (float*)(sm + OFF_Z);   // [BPC][COLS]
    float* wxs  = (float*)(sm + OFF_WX);  // [3][COLS]
    float* bis  = (float*)(sm + OFF_BI);  // [COLS]
    float* xss  = (float*)(sm + OFF_XS);  // [BPC][4]

    const int tid   = threadIdx.x;
    const int crank = blockIdx.x & (CLS - 1);
    const int cid   = blockIdx.x >> 3;
    const int bBase = cid * BPC;
    const int uBase = crank * UCTA;

    // ---- Prologue: stage weights (once) ----
    // Wh slice pair-packed along k: Wp[k2][c] = (Wh[2k2, gcol], Wh[2k2+1, gcol])
    for (int idx = tid; idx < 128 * 128; idx += NTHR) {
        int k2 = idx >> 7, c = idx & 127;
        int g = c >> 5, uu = c & 31;
        int gcol = g * UU + uBase + uu;
        Wp[idx * 2 + 0] = Wh[(size_t)(2 * k2) * 1024 + gcol];
        Wp[idx * 2 + 1] = Wh[(size_t)(2 * k2 + 1) * 1024 + gcol];
    }
    for (int idx = tid; idx < 3 * COLS; idx += NTHR) {
        int f = idx >> 7, c = idx & 127;
        int g = c >> 5, uu = c & 31;
        wxs[idx] = Wx[f * 1024 + g * UU + uBase + uu];
    }
    if (tid < COLS) {
        int g = tid >> 5, uu = tid & 31;
        bis[tid] = bias[g * UU + uBase + uu];
    }
    for (int idx = tid; idx < 2 * BPC * UU; idx += NTHR) hbuf[idx] = 0.f;
    __syncthreads();
    // all cluster CTAs initialized before any DSMEM traffic
    asm volatile("barrier.cluster.arrive.aligned;" ::: "memory");
    asm volatile("barrier.cluster.wait.aligned;"   ::: "memory");

    // ---- GEMM thread mapping: 4 batches x 1 column per thread ----
    const int w    = tid >> 5;
    const int lane = tid & 31;
    const int c    = ((w & 3) << 5) | lane;   // 0..127
    const int b0   = (w >> 2) << 2;           // 0 or 4

    // ---- Epilogue mapping: (batch, u) per thread; c-state in register ----
    const int eb = tid >> 5;        // 0..7
    const int eu = tid & 31;        // 0..31
    const int gu = uBase + eu;      // global u (also index in replicated h buffer)
    const int gb = bBase + eb;      // global batch
    const uint32_t haddr0 = smem_u32(hbuf + 0 * BPC * UU + eb * UU + gu);
    const uint32_t haddr1 = smem_u32(hbuf + 1 * BPC * UU + eb * UU + gu);

    const unsigned long long* __restrict__ Wq = (const unsigned long long*)Wp;

    float creg = 0.f, hreg = 0.f;

    for (int t = 0; t < TT; ++t) {
        const int pp = t & 1;
        const int np = pp ^ 1;

        // prefetch this step's x values (consumed after the barrier below)
        float xv = 0.f; int xb = 0, xf = 0;
        if (tid < BPC * 3) {
            xb = tid / 3; xf = tid - xb * 3;
            xv = x[((size_t)(bBase + xb) * TT + t) * 3 + xf];
        }

        // ---- z[b0..b0+3][c] = h[b][:] . Wslice[:][c]  (f32x2 packed MACs) ----
        const unsigned long long* __restrict__ hq =
            (const unsigned long long*)(hbuf + pp * BPC * UU);
        const unsigned long long* __restrict__ h0 = hq + (b0 + 0) * 128;
        const unsigned long long* __restrict__ h1 = hq + (b0 + 1) * 128;
        const unsigned long long* __restrict__ h2 = hq + (b0 + 2) * 128;
        const unsigned long long* __restrict__ h3 = hq + (b0 + 3) * 128;
        const unsigned long long* __restrict__ wp = Wq + c;

        unsigned long long a0 = 0ull, a1 = 0ull, a2 = 0ull, a3 = 0ull;
        #pragma unroll 8
        for (int k2 = 0; k2 < 128; ++k2) {
            unsigned long long wv = wp[(size_t)k2 * 128];
            ffma2(a0, h0[k2], wv);
            ffma2(a1, h1[k2], wv);
            ffma2(a2, h2[k2], wv);
            ffma2(a3, h3[k2], wv);
        }
        { float2 f = *(float2*)&a0; zs[(b0 + 0) * COLS + c] = f.x + f.y; }
        { float2 f = *(float2*)&a1; zs[(b0 + 1) * COLS + c] = f.x + f.y; }
        { float2 f = *(float2*)&a2; zs[(b0 + 2) * COLS + c] = f.x + f.y; }
        { float2 f = *(float2*)&a3; zs[(b0 + 3) * COLS + c] = f.x + f.y; }
        if (tid < BPC * 3) xss[xb * 4 + xf] = xv;
        __syncthreads();

        // ---- gates + state update for this CTA's (8 b x 32 u) slice ----
        float x0 = xss[eb * 4 + 0], x1 = xss[eb * 4 + 1], x2 = xss[eb * 4 + 2];
        float zg[4];
        #pragma unroll
        for (int g = 0; g < 4; ++g) {
            int cc = g * 32 + eu;
            zg[g] = zs[eb * COLS + cc] + bis[cc]
                  + x0 * wxs[cc] + x1 * wxs[128 + cc] + x2 * wxs[256 + cc];
        }
        float ig = sigm(zg[0]);
        float fg = sigm(zg[1]);
        float gg = tanh_f(zg[2]);
        float og = sigm(zg[3]);
        creg = fg * creg + ig * gg;
        hreg = og * tanh_f(creg);

        // broadcast new h element to all 8 cluster CTAs' next-buffer
        uint32_t hdst = np ? haddr1 : haddr0;
        #pragma unroll
        for (uint32_t r = 0; r < CLS; ++r) st_cluster_f32(hdst, r, hreg);

        // write ys[b][t][u]
        out[((size_t)gb * TT + t) * UU + gu] = hreg;

        // step barrier: release DSMEM stores / acquire peers' h
        asm volatile("barrier.cluster.arrive.aligned;" ::: "memory");
        asm volatile("barrier.cluster.wait.aligned;"   ::: "memory");
    }

    // final h_T, c_T (after ys block), only if the harness buffer includes them
    if (out_size >= BB * TT * UU + 2 * BB * UU) {
        size_t base = (size_t)BB * TT * UU;
        out[base + (size_t)gb * UU + gu] = hreg;
        out[base + (size_t)BB * UU + (size_t)gb * UU + gu] = creg;
    }
}

extern "C" void kernel_launch(void* const* d_in, const int* in_sizes, int n_in,
                              void* d_out, int out_size)
{
    // Identify inputs by element count (robust to ordering):
    const float* x  = nullptr;  // 128*2048*3 = 786432
    const float* wx = nullptr;  // 3*1024    = 3072
    const float* wh = nullptr;  // 256*1024  = 262144
    const float* bi = nullptr;  // 1024
    for (int i = 0; i < n_in; ++i) {
        switch (in_sizes[i]) {
            case 786432: x  = (const float*)d_in[i]; break;
            case 3072:   wx = (const float*)d_in[i]; break;
            case 262144: wh = (const float*)d_in[i]; break;
            case 1024:   bi = (const float*)d_in[i]; break;
            default: break;
        }
    }
    if (!x)  x  = (const float*)d_in[0];
    if (!wx) wx = (const float*)d_in[1];
    if (!wh) wh = (const float*)d_in[2];
    if (!bi) bi = (const float*)d_in[3];

    cudaFuncSetAttribute(lstm_cluster_kernel,
                         cudaFuncAttributeMaxDynamicSharedMemorySize, SMEM_BYTES);

    lstm_cluster_kernel<<<BB / BPC * CLS, NTHR, SMEM_BYTES>>>(
        x, wx, wh, bi, (float*)d_out, out_size);
}

// round 4
// speedup vs baseline: 1.2063x; 1.2063x over previous
#include <cuda_runtime.h>
#include <cstdint>
#include <cstddef>

// Problem constants
#define BB   128      // batch
#define TT   2048     // timesteps
#define UU   256      // units
#define CLS  8        // cluster size (u-split)
#define BPC  8        // batches per cluster
#define UCTA 32       // u per CTA
#define COLS 128      // z columns per CTA (4 gates * 32 u)
#define NTHR 512      // 16 warps: 128 cols x 4 k-splits
#define KSPL 4        // k-split factor
#define KPT  64       // k per thread (256/KSPL)

typedef unsigned long long ull;

__device__ __forceinline__ void ffma2(ull &acc, ull a, ull w) {
    asm("fma.rn.f32x2 %0, %1, %2, %0;" : "+l"(acc) : "l"(a), "l"(w));
}

__device__ __forceinline__ uint32_t smem_u32(const void* p) {
    uint32_t a;
    asm("{ .reg .u64 t; cvta.to.shared.u64 t, %1; cvt.u32.u64 %0, t; }"
        : "=r"(a) : "l"(p));
    return a;
}

__device__ __forceinline__ void st_cluster_f32(uint32_t saddr, uint32_t rank, float v) {
    uint32_t r;
    asm volatile("mapa.shared::cluster.u32 %0, %1, %2;" : "=r"(r) : "r"(saddr), "r"(rank));
    asm volatile("st.shared::cluster.b32 [%0], %1;" :: "r"(r), "r"(__float_as_uint(v)) : "memory");
}

__device__ __forceinline__ float sigm(float v) {
    return 1.f / (1.f + __expf(-v));
}

__device__ __forceinline__ float tanh_f(float v) {
    float vv = fminf(fmaxf(v, -15.f), 15.f);
    float e = __expf(-2.f * vv);
    return (1.f - e) / (1.f + e);
}

__global__ void __launch_bounds__(NTHR, 1) __cluster_dims__(CLS, 1, 1)
lstm_cluster_kernel(const float* __restrict__ x,     // [B,T,3]
                    const float* __restrict__ Wx,    // [3,1024]
                    const float* __restrict__ Wh,    // [256,1024]
                    const float* __restrict__ bias,  // [1024]
                    float* __restrict__ out, int out_size)
{
    // Static shared: h double-buffer + z partials + small stuff (~35 KB)
    __shared__ float hbuf[2][BPC][UU];       // 16 KB (replicated h, DSMEM target)
    __shared__ float zpart[KSPL][BPC][COLS]; // 16 KB
    __shared__ float wxs[3][COLS];           // Wx slice
    __shared__ float bis[COLS];
    __shared__ float xss[BPC][4];

    const int tid   = threadIdx.x;
    const int crank = blockIdx.x & (CLS - 1);
    const int cid   = blockIdx.x >> 3;
    const int bBase = cid * BPC;
    const int uBase = crank * UCTA;

    // GEMM mapping: column + k-quarter per thread, all 8 batches
    const int c   = tid & 127;          // 0..127  (gate*32 + u)
    const int kh  = tid >> 7;           // 0..3    (k quarter)
    const int g   = c >> 5;
    const int gcol = g * UU + uBase + (c & 31);

    // ---- Prologue ----
    // W slice into REGISTERS: 32 packed f32x2 pairs covering k in [kh*64, kh*64+64)
    ull wq[KPT / 2];
    {
        const int k0 = kh * KPT;
        #pragma unroll
        for (int j = 0; j < KPT / 2; ++j) {
            float w0 = Wh[(size_t)(k0 + 2 * j) * 1024 + gcol];
            float w1 = Wh[(size_t)(k0 + 2 * j + 1) * 1024 + gcol];
            float2 p = make_float2(w0, w1);
            wq[j] = *(ull*)&p;
        }
    }
    for (int idx = tid; idx < 3 * COLS; idx += NTHR) {
        int f = idx >> 7, cc = idx & 127;
        wxs[f][cc] = Wx[f * 1024 + (cc >> 5) * UU + uBase + (cc & 31)];
    }
    if (tid < COLS) bis[tid] = bias[(tid >> 5) * UU + uBase + (tid & 31)];
    for (int idx = tid; idx < 2 * BPC * UU; idx += NTHR) ((float*)hbuf)[idx] = 0.f;
    __syncthreads();
    asm volatile("barrier.cluster.arrive.aligned;" ::: "memory");
    asm volatile("barrier.cluster.wait.aligned;"   ::: "memory");

    // Epilogue mapping (threads 0..255): (batch, u)
    const int eb = tid >> 5;            // 0..7 (valid when tid<256)
    const int eu = tid & 31;
    const int gu = uBase + eu;
    const int gb = bBase + (eb & 7);
    const uint32_t haddr0 = smem_u32(&hbuf[0][eb & 7][gu]);
    const uint32_t haddr1 = smem_u32(&hbuf[1][eb & 7][gu]);

    float creg = 0.f, hreg = 0.f;

    for (int t = 0; t < TT; ++t) {
        const int pp = t & 1;
        const int np = pp ^ 1;

        // prefetch x for this step (24 threads)
        float xv = 0.f; int xb = 0, xf = 0;
        if (tid < BPC * 3) {
            xb = tid / 3; xf = tid - xb * 3;
            xv = x[((size_t)(bBase + xb) * TT + t) * 3 + xf];
        }

        // ---- GEMM: zpart[kh][b][c] = sum_{k in quarter} h[b][k] * W[k][c] ----
        // h loads: float4 broadcasts; W entirely in registers.
        const float4* __restrict__ h4 = (const float4*)&hbuf[pp][0][0];
        // h4 index for batch b, quad q: b*64 + kh*16 + q
        ull acc[BPC];
        #pragma unroll
        for (int b = 0; b < BPC; ++b) acc[b] = 0ull;

        const int qbase = kh * 16;
        #pragma unroll
        for (int q = 0; q < 16; ++q) {
            #pragma unroll
            for (int b = 0; b < BPC; ++b) {
                float4 hv = h4[b * 64 + qbase + q];
                ull lo = *(ull*)&hv;
                ull hi = *((ull*)&hv + 1);
                ffma2(acc[b], lo, wq[2 * q]);
                ffma2(acc[b], hi, wq[2 * q + 1]);
            }
        }
        #pragma unroll
        for (int b = 0; b < BPC; ++b) {
            float2 f = *(float2*)&acc[b];
            zpart[kh][b][c] = f.x + f.y;
        }
        if (tid < BPC * 3) xss[xb][xf] = xv;
        __syncthreads();

        // ---- reduce + gates + state update (threads 0..255) ----
        if (tid < 256) {
            float x0 = xss[eb][0], x1 = xss[eb][1], x2 = xss[eb][2];
            float zg[4];
            #pragma unroll
            for (int gg = 0; gg < 4; ++gg) {
                int cc = gg * 32 + eu;
                float z = bis[cc] + x0 * wxs[0][cc] + x1 * wxs[1][cc] + x2 * wxs[2][cc];
                #pragma unroll
                for (int k = 0; k < KSPL; ++k) z += zpart[k][eb][cc];
                zg[gg] = z;
            }
            float ig = sigm(zg[0]);
            float fg = sigm(zg[1]);
            float gv = tanh_f(zg[2]);
            float og = sigm(zg[3]);
            creg = fg * creg + ig * gv;
            hreg = og * tanh_f(creg);

            // broadcast h element to all 8 cluster CTAs (next buffer)
            uint32_t hdst = np ? haddr1 : haddr0;
            #pragma unroll
            for (uint32_t r = 0; r < CLS; ++r) st_cluster_f32(hdst, r, hreg);

            out[((size_t)gb * TT + t) * UU + gu] = hreg;
        }

        // step barrier: DSMEM release/acquire across the cluster
        asm volatile("barrier.cluster.arrive.aligned;" ::: "memory");
        asm volatile("barrier.cluster.wait.aligned;"   ::: "memory");
    }

    // final h_T, c_T after ys block, if the output buffer includes them
    if (tid < 256 && out_size >= BB * TT * UU + 2 * BB * UU) {
        size_t base = (size_t)BB * TT * UU;
        out[base + (size_t)gb * UU + gu] = hreg;
        out[base + (size_t)BB * UU + (size_t)gb * UU + gu] = creg;
    }
}

extern "C" void kernel_launch(void* const* d_in, const int* in_sizes, int n_in,
                              void* d_out, int out_size)
{
    const float* x  = nullptr;  // 786432
    const float* wx = nullptr;  // 3072
    const float* wh = nullptr;  // 262144
    const float* bi = nullptr;  // 1024
    for (int i = 0; i < n_in; ++i) {
        switch (in_sizes[i]) {
            case 786432: x  = (const float*)d_in[i]; break;
            case 3072:   wx = (const float*)d_in[i]; break;
            case 262144: wh = (const float*)d_in[i]; break;
            case 1024:   bi = (const float*)d_in[i]; break;
            default: break;
        }
    }
    if (!x)  x  = (const float*)d_in[0];
    if (!wx) wx = (const float*)d_in[1];
    if (!wh) wh = (const float*)d_in[2];
    if (!bi) bi = (const float*)d_in[3];

    lstm_cluster_kernel<<<BB / BPC * CLS, NTHR>>>(
        x, wx, wh, bi, (float*)d_out, out_size);
}

// round 5
// speedup vs baseline: 1.5640x; 1.2965x over previous
#include <cuda_runtime.h>
#include <cstdint>
#include <cstddef>

// Problem constants
#define BB   128      // batch
#define TT   2048     // timesteps
#define UU   256      // units
#define CLS  8        // cluster size (u-split)
#define BPC  8        // batches per cluster
#define UCTA 32       // u per CTA
#define COLS 128      // z columns per CTA (4 gates * 32 u)
#define NTHR 512      // 16 warps: 128 cols x 4 k-splits
#define KSPL 4
#define KPT  64       // k per thread

// Dynamic shared memory layout (bytes)
#define OFF_H    0                         // h double buffer [2][8][256] f32
#define OFF_Z    (OFF_H  + 2*BPC*UU*4)     // zpart [2][KSPL][BPC][COLS] f32  (32 KB)
#define OFF_WX   (OFF_Z  + 2*KSPL*BPC*COLS*4)
#define OFF_BI   (OFF_WX + 3*COLS*4)
#define OFF_XS   (OFF_BI + COLS*4)         // xss [2][8][4] f32
#define OFF_MB   (OFF_XS + 2*BPC*4*4)      // 2 mbarriers (16B, 8B aligned)
#define SMEM_BYTES (OFF_MB + 64)

typedef unsigned long long ull;

__device__ __forceinline__ void ffma2(ull &acc, ull a, ull w) {
    asm("fma.rn.f32x2 %0, %1, %2, %0;" : "+l"(acc) : "l"(a), "l"(w));
}

__device__ __forceinline__ uint32_t smem_u32(const void* p) {
    uint32_t a;
    asm("{ .reg .u64 t; cvta.to.shared.u64 t, %1; cvt.u32.u64 %0, t; }"
        : "=r"(a) : "l"(p));
    return a;
}

// Store one f32 into CTA `rank`'s smem, signaling that CTA's mbarrier with 4 tx bytes.
__device__ __forceinline__ void st_async_h(uint32_t daddr, uint32_t mbar,
                                           uint32_t rank, float v) {
    uint32_t ra, rm;
    asm volatile("mapa.shared::cluster.u32 %0, %1, %2;" : "=r"(ra) : "r"(daddr), "r"(rank));
    asm volatile("mapa.shared::cluster.u32 %0, %1, %2;" : "=r"(rm) : "r"(mbar), "r"(rank));
    asm volatile("st.async.shared::cluster.mbarrier::complete_tx::bytes.b32 [%0], %1, [%2];"
                 :: "r"(ra), "r"(__float_as_uint(v)), "r"(rm) : "memory");
}

__device__ __forceinline__ void mbar_init(uint32_t mbar, uint32_t cnt) {
    asm volatile("mbarrier.init.shared.b64 [%0], %1;" :: "r"(mbar), "r"(cnt) : "memory");
}
__device__ __forceinline__ void mbar_arrive_expect(uint32_t mbar, uint32_t tx) {
    asm volatile("mbarrier.arrive.expect_tx.shared.b64 _, [%0], %1;"
                 :: "r"(mbar), "r"(tx) : "memory");
}
__device__ __forceinline__ void mbar_wait(uint32_t mbar, uint32_t parity) {
    asm volatile(
        "{\n\t"
        ".reg .pred P;\n\t"
        "WL_%=:\n\t"
        "mbarrier.try_wait.parity.acquire.cta.shared::cta.b64 P, [%0], %1, 0x989680;\n\t"
        "@P bra.uni WD_%=;\n\t"
        "bra.uni WL_%=;\n\t"
        "WD_%=:\n\t"
        "}" :: "r"(mbar), "r"(parity) : "memory");
}

__device__ __forceinline__ float sigm(float v) { return 1.f / (1.f + __expf(-v)); }
__device__ __forceinline__ float tanh_f(float v) {
    float vv = fminf(fmaxf(v, -15.f), 15.f);
    float e = __expf(-2.f * vv);
    return (1.f - e) / (1.f + e);
}

__global__ void __launch_bounds__(NTHR, 1) __cluster_dims__(CLS, 1, 1)
lstm_cluster_kernel(const float* __restrict__ x,     // [B,T,3]
                    const float* __restrict__ Wx,    // [3,1024]
                    const float* __restrict__ Wh,    // [256,1024]
                    const float* __restrict__ bias,  // [1024]
                    float* __restrict__ out, int out_size)
{
    extern __shared__ char sm[];
    float* hbuf  = (float*)(sm + OFF_H);    // [2][BPC][UU]
    float* zpart = (float*)(sm + OFF_Z);    // [2][KSPL][BPC][COLS]
    float* wxs   = (float*)(sm + OFF_WX);   // [3][COLS]
    float* bis   = (float*)(sm + OFF_BI);   // [COLS]
    float* xss   = (float*)(sm + OFF_XS);   // [2][BPC][4]

    const int tid   = threadIdx.x;
    const int crank = blockIdx.x & (CLS - 1);
    const int cid   = blockIdx.x >> 3;
    const int bBase = cid * BPC;
    const int uBase = crank * UCTA;

    const uint32_t mb0 = smem_u32(sm + OFF_MB);
    const uint32_t mb1 = mb0 + 8;

    // GEMM mapping: (column, k-quarter) per thread
    const int c    = tid & 127;
    const int kh   = tid >> 7;
    const int gcol = (c >> 5) * UU + uBase + (c & 31);

    // ---- Prologue ----
    // Wh slice into registers: 32 f32x2 pairs, k in [kh*64, kh*64+64)
    ull wq[KPT / 2];
    {
        const int k0 = kh * KPT;
        #pragma unroll
        for (int j = 0; j < KPT / 2; ++j) {
            float2 p = make_float2(Wh[(size_t)(k0 + 2 * j) * 1024 + gcol],
                                   Wh[(size_t)(k0 + 2 * j + 1) * 1024 + gcol]);
            wq[j] = *(ull*)&p;
        }
    }
    for (int idx = tid; idx < 3 * COLS; idx += NTHR) {
        int f = idx >> 7, cc = idx & 127;
        wxs[idx] = Wx[f * 1024 + (cc >> 5) * UU + uBase + (cc & 31)];
    }
    if (tid < COLS) bis[tid] = bias[(tid >> 5) * UU + uBase + (tid & 31)];
    for (int idx = tid; idx < 2 * BPC * UU; idx += NTHR) hbuf[idx] = 0.f;
    if (tid == 0) {
        mbar_init(mb0, 1);
        mbar_init(mb1, 1);
        mbar_arrive_expect(mb0, BPC * UU * 4);   // arm phase 0, both buffers
        mbar_arrive_expect(mb1, BPC * UU * 4);
    }
    __syncthreads();
    asm volatile("barrier.cluster.arrive.aligned;" ::: "memory");
    asm volatile("barrier.cluster.wait.aligned;"   ::: "memory");

    // Epilogue mapping (threads 0..255): (batch, u)
    const int eb = (tid >> 5) & 7;
    const int eu = tid & 31;
    const int gu = uBase + eu;
    const int gb = bBase + eb;
    const uint32_t haddr0 = smem_u32(hbuf + 0 * BPC * UU + eb * UU + gu);
    const uint32_t haddr1 = smem_u32(hbuf + 1 * BPC * UU + eb * UU + gu);

    float creg = 0.f, hreg = 0.f;
    uint32_t ph0 = 0, ph1 = 0;   // wait parity per buffer

    for (int t = 0; t < TT; ++t) {
        const int pp = t & 1;

        // x prefetch (24 threads) — LDG issued before the wait to hide L2 latency
        float xv = 0.f; int xb = 0, xf = 0;
        if (tid < BPC * 3) {
            xb = tid / 3; xf = tid - xb * 3;
            xv = x[((size_t)(bBase + xb) * TT + t) * 3 + xf];
        }

        // Wait for this step's h buffer (filled by all 8 CTAs' st.async at step t-1).
        // Re-arm immediately after the wait (ordered before our own next stores by
        // the __syncthreads below).
        if (t > 0) {
            uint32_t mb = pp ? mb1 : mb0;
            uint32_t ph = pp ? ph1 : ph0;
            mbar_wait(mb, ph);
            if (pp) ph1 ^= 1; else ph0 ^= 1;
            if (tid == 0) mbar_arrive_expect(mb, BPC * UU * 4);
        }

        // ---- GEMM: zpart[pp][kh][b][c] = sum_{k quarter} h[b][k] * W[k][c] ----
        const float4* __restrict__ h4 = (const float4*)(hbuf + pp * BPC * UU);
        const int qbase = kh * 16;
        float* __restrict__ zp = zpart + ((pp * KSPL + kh) * BPC) * COLS + c;
        #pragma unroll
        for (int grp = 0; grp < 2; ++grp) {
            ull a0 = 0ull, a1 = 0ull, a2 = 0ull, a3 = 0ull;
            const float4* __restrict__ hg = h4 + (grp * 4) * 64 + qbase;
            #pragma unroll
            for (int q = 0; q < 16; ++q) {
                ull w0 = wq[2 * q], w1 = wq[2 * q + 1];
                float4 v0 = hg[0 * 64 + q];
                float4 v1 = hg[1 * 64 + q];
                float4 v2 = hg[2 * 64 + q];
                float4 v3 = hg[3 * 64 + q];
                ffma2(a0, *(ull*)&v0, w0); ffma2(a0, *((ull*)&v0 + 1), w1);
                ffma2(a1, *(ull*)&v1, w0); ffma2(a1, *((ull*)&v1 + 1), w1);
                ffma2(a2, *(ull*)&v2, w0); ffma2(a2, *((ull*)&v2 + 1), w1);
                ffma2(a3, *(ull*)&v3, w0); ffma2(a3, *((ull*)&v3 + 1), w1);
            }
            { float2 f = *(float2*)&a0; zp[(grp * 4 + 0) * COLS] = f.x + f.y; }
            { float2 f = *(float2*)&a1; zp[(grp * 4 + 1) * COLS] = f.x + f.y; }
            { float2 f = *(float2*)&a2; zp[(grp * 4 + 2) * COLS] = f.x + f.y; }
            { float2 f = *(float2*)&a3; zp[(grp * 4 + 3) * COLS] = f.x + f.y; }
        }
        if (tid < BPC * 3) xss[(pp * BPC + xb) * 4 + xf] = xv;
        __syncthreads();

        // ---- epilogue: reduce + gates + state + h broadcast (threads 0..255) ----
        if (tid < 256) {
            const float* xr = xss + (pp * BPC + eb) * 4;
            float x0 = xr[0], x1 = xr[1], x2 = xr[2];
            const float* zb = zpart + (pp * KSPL * BPC) * COLS + eb * COLS;
            float zg[4];
            #pragma unroll
            for (int g = 0; g < 4; ++g) {
                int cc = g * 32 + eu;
                float z = bis[cc] + x0 * wxs[cc] + x1 * wxs[128 + cc] + x2 * wxs[256 + cc];
                #pragma unroll
                for (int k = 0; k < KSPL; ++k) z += zb[k * BPC * COLS + cc];
                zg[g] = z;
            }
            float ig = sigm(zg[0]);
            float fg = sigm(zg[1]);
            float gv = tanh_f(zg[2]);
            float og = sigm(zg[3]);
            creg = fg * creg + ig * gv;
            hreg = og * tanh_f(creg);

            // broadcast h to all 8 CTAs' next buffer, signaling their mbarrier
            uint32_t hdst = pp ? haddr0 : haddr1;   // next buffer
            uint32_t mbn  = pp ? mb0 : mb1;
            #pragma unroll
            for (uint32_t r = 0; r < CLS; ++r) st_async_h(hdst, mbn, r, hreg);

            out[((size_t)gb * TT + t) * UU + gu] = hreg;
        }
    }

    // keep all cluster CTAs alive until the last in-flight st.async lands
    asm volatile("barrier.cluster.arrive.aligned;" ::: "memory");
    asm volatile("barrier.cluster.wait.aligned;"   ::: "memory");

    if (tid < 256 && out_size >= BB * TT * UU + 2 * BB * UU) {
        size_t base = (size_t)BB * TT * UU;
        out[base + (size_t)gb * UU + gu] = hreg;
        out[base + (size_t)BB * UU + (size_t)gb * UU + gu] = creg;
    }
}

extern "C" void kernel_launch(void* const* d_in, const int* in_sizes, int n_in,
                              void* d_out, int out_size)
{
    const float* x  = nullptr;  // 786432
    const float* wx = nullptr;  // 3072
    const float* wh = nullptr;  // 262144
    const float* bi = nullptr;  // 1024
    for (int i = 0; i < n_in; ++i) {
        switch (in_sizes[i]) {
            case 786432: x  = (const float*)d_in[i]; break;
            case 3072:   wx = (const float*)d_in[i]; break;
            case 262144: wh = (const float*)d_in[i]; break;
            case 1024:   bi = (const float*)d_in[i]; break;
            default: break;
        }
    }
    if (!x)  x  = (const float*)d_in[0];
    if (!wx) wx = (const float*)d_in[1];
    if (!wh) wh = (const float*)d_in[2];
    if (!bi) bi = (const float*)d_in[3];

    cudaFuncSetAttribute(lstm_cluster_kernel,
                         cudaFuncAttributeMaxDynamicSharedMemorySize, SMEM_BYTES);

    lstm_cluster_kernel<<<BB / BPC * CLS, NTHR, SMEM_BYTES>>>(
        x, wx, wh, bi, (float*)d_out, out_size);
}